// round 13
// baseline (speedup 1.0000x reference)
#include <cuda_runtime.h>
#include <cuda_fp16.h>
#include <math.h>

#define MAX_VERT 500000
#define ELL_CAP 48
#define LAMBDA_REG_LEN 1e-6f

// scratch (no cudaMalloc allowed)
__device__ double g_acc;
__device__ int    g_idx64;                 // 1 if neigh is int64, 0 if int32
__device__ int    g_deg[MAX_VERT];
// slot-major ELL: g_ell[slot * MAX_VERT + v] -> coalesced reads in k_svd
__device__ __align__(16) int    g_ell[ELL_CAP * MAX_VERT];
// packed fp16 mesh: (vt.x,vt.y)(vt.z,v0.x)(v0.y,v0.z)(pad) per vertex, 16B
__device__ __align__(16) float4 g_PH[MAX_VERT];
// packed fp16 (quat w,x)(quat y,z)(v0.x,v0.y)(v0.z,pad) per vertex, 16B
__device__ __align__(16) float4 g_EQ[MAX_VERT];

// ---------------------------------------------------------------------------
// fp16 pack/unpack helpers
// ---------------------------------------------------------------------------
__device__ __forceinline__ float pack2(float a, float b)
{
    __half2 h = __floats2half2_rn(a, b);
    return __uint_as_float(*reinterpret_cast<unsigned*>(&h));
}
__device__ __forceinline__ float2 unpack2(float f)
{
    unsigned u = __float_as_uint(f);
    __half2 h = *reinterpret_cast<__half2*>(&u);
    return __half22float2(h);
}

__device__ __forceinline__ void load_edge(const void* __restrict__ neigh,
                                          int e, int idx64, int& i, int& j)
{
    if (idx64) {
        const longlong2* p = (const longlong2*)neigh;
        longlong2 v = p[e];
        i = (int)v.x;
        j = (int)v.y;
    } else {
        const int2* p = (const int2*)neigh;
        int2 v = p[e];
        i = v.x;
        j = v.y;
    }
}

__device__ __forceinline__ void block_reduce_to_acc(float val)
{
    __shared__ float sdata[256];
    int tid = threadIdx.x;
    sdata[tid] = val;
    __syncthreads();
    for (int s = 128; s > 0; s >>= 1) {
        if (tid < s) sdata[tid] += sdata[tid + s];
        __syncthreads();
    }
    if (tid == 0)
        atomicAdd(&g_acc, (double)sdata[0]);
}

// ---------------------------------------------------------------------------
// Kernel 1: pack vertex arrays into fp16 records; zero degrees.
// Block 0 additionally performs the index-dtype detection (int64 LE => all
// odd 32-bit words of neigh are zero) and resets the accumulator.
// ---------------------------------------------------------------------------
__global__ void k_pack(const float* __restrict__ vt,
                       const float* __restrict__ v0,
                       const unsigned int* __restrict__ neigh_raw,
                       int n_words,
                       int n_vert)
{
    if (blockIdx.x == 0) {
        __shared__ int any_nonzero;
        if (threadIdx.x == 0) any_nonzero = 0;
        __syncthreads();
        int limit = n_words < 2048 ? n_words : 2048;
        for (int w = threadIdx.x; w < limit; w += blockDim.x) {
            if ((w & 1) && neigh_raw[w] != 0u) atomicOr(&any_nonzero, 1);
        }
        __syncthreads();
        if (threadIdx.x == 0) {
            g_idx64 = any_nonzero ? 0 : 1;
            g_acc   = 0.0;
        }
    }

    int v = blockIdx.x * blockDim.x + threadIdx.x;
    if (v >= n_vert) return;
    float tx = vt[3 * v], ty = vt[3 * v + 1], tz = vt[3 * v + 2];
    float ox = v0[3 * v], oy = v0[3 * v + 1], oz = v0[3 * v + 2];
    float4 r;
    r.x = pack2(tx, ty);
    r.y = pack2(tz, ox);
    r.z = pack2(oy, oz);
    r.w = 0.f;
    g_PH[v]  = r;
    g_deg[v] = 0;
}

// ---------------------------------------------------------------------------
// Kernel 2: build ELL adjacency (slot-major), two edges per thread.
// ---------------------------------------------------------------------------
__global__ void k_fill(const void* __restrict__ neigh, int n_edge, int half)
{
    int e0 = blockIdx.x * blockDim.x + threadIdx.x;
    if (e0 >= half) return;
    int e1 = e0 + half;
    bool has1 = (e1 < n_edge);

    int idx64 = g_idx64;
    int i0, j0, i1 = 0, j1 = 0;
    load_edge(neigh, e0, idx64, i0, j0);
    if (has1) load_edge(neigh, e1, idx64, i1, j1);

    int p0 = atomicAdd(&g_deg[i0], 1);
    int q0 = atomicAdd(&g_deg[j0], 1);
    int p1 = 0, q1 = 0;
    if (has1) {
        p1 = atomicAdd(&g_deg[i1], 1);
        q1 = atomicAdd(&g_deg[j1], 1);
    }

    if (p0 < ELL_CAP) g_ell[p0 * MAX_VERT + i0] = j0;
    if (q0 < ELL_CAP) g_ell[q0 * MAX_VERT + j0] = i0;
    if (has1) {
        if (p1 < ELL_CAP) g_ell[p1 * MAX_VERT + i1] = j1;
        if (q1 < ELL_CAP) g_ell[q1 * MAX_VERT + j1] = i1;
    }
}

// ---------------------------------------------------------------------------
// Kernel 3: fused gather + SVD, TWO THREADS PER VERTEX.
// Each thread of a lane pair gathers every other ELL slot; the pair merges
// S and the energy part via shfl_xor, then both redundantly run the small
// Jacobi polar solve (no divergence); the even lane commits results.
// ---------------------------------------------------------------------------
template <int p, int q>
__device__ __forceinline__ void jrot(float (&A)[3][3], float (&V)[3][3])
{
    float apq = A[p][q];
    if (fabsf(apq) < 1e-30f) return;
    float tau = (A[q][q] - A[p][p]) * 0.5f / apq;
    float t   = copysignf(1.0f, tau) / (fabsf(tau) + sqrtf(1.0f + tau * tau));
    float c   = rsqrtf(1.0f + t * t);
    float s   = t * c;

    constexpr int k = 3 - p - q;
    float akp = A[k][p], akq = A[k][q];
    float nkp = c * akp - s * akq;
    float nkq = s * akp + c * akq;
    A[k][p] = nkp; A[p][k] = nkp;
    A[k][q] = nkq; A[q][k] = nkq;
    A[p][p] = A[p][p] - t * apq;
    A[q][q] = A[q][q] + t * apq;
    A[p][q] = 0.0f; A[q][p] = 0.0f;

#pragma unroll
    for (int r = 0; r < 3; r++) {
        float vp = V[r][p], vq = V[r][q];
        V[r][p] = c * vp - s * vq;
        V[r][q] = s * vp + c * vq;
    }
}

__device__ __forceinline__ void decode_ph(float4 r,
                                          float& tx, float& ty, float& tz,
                                          float& ox, float& oy, float& oz)
{
    float2 a = unpack2(r.x);
    float2 b = unpack2(r.y);
    float2 c = unpack2(r.z);
    tx = a.x; ty = a.y; tz = b.x;
    ox = b.y; oy = c.x; oz = c.y;
}

__global__ void k_svd(int n_vert)
{
    int gid = blockIdx.x * blockDim.x + threadIdx.x;
    int v   = gid >> 1;
    int par = gid & 1;
    float contrib = 0.0f;

    if (v < n_vert) {
        float ptx, pty, ptz, p0x, p0y, p0z;
        decode_ph(g_PH[v], ptx, pty, ptz, p0x, p0y, p0z);

        int deg = g_deg[v];
        if (deg > ELL_CAP) deg = ELL_CAP;
        // slots for this thread: par, par+2, par+4, ...
        int n_my = (deg - par + 1) >> 1;          // ceil((deg-par)/2)
        int padded_my = (n_my + 3) & ~3;

        float S[3][3] = {{0, 0, 0}, {0, 0, 0}, {0, 0, 0}};
        float epart = 0.0f;

        for (int t0 = 0; t0 < padded_my; t0 += 4) {
            int ids[4];
#pragma unroll
            for (int t = 0; t < 4; t++) {
                int k = t0 + t;
                ids[t] = (k < n_my) ? g_ell[(2 * k + par) * MAX_VERT + v] : v;
            }
            float4 ph[4];
#pragma unroll
            for (int t = 0; t < 4; t++) ph[t] = g_PH[ids[t]];
#pragma unroll
            for (int t = 0; t < 4; t++) {
                float qtx, qty, qtz, q0x, q0y, q0z;
                decode_ph(ph[t], qtx, qty, qtz, q0x, q0y, q0z);
                float dt0 = ptx - qtx, dt1 = pty - qty, dt2 = ptz - qtz;
                float d00 = p0x - q0x, d01 = p0y - q0y, d02 = p0z - q0z;
                S[0][0] += dt0 * d00; S[0][1] += dt0 * d01; S[0][2] += dt0 * d02;
                S[1][0] += dt1 * d00; S[1][1] += dt1 * d01; S[1][2] += dt1 * d02;
                S[2][0] += dt2 * d00; S[2][1] += dt2 * d01; S[2][2] += dt2 * d02;
                epart += 0.5f  * (dt0 * dt0 + dt1 * dt1 + dt2 * dt2)
                       + 0.25f * (d00 * d00 + d01 * d01 + d02 * d02);
            }
        }

        // pair merge (lane ^ 1): both lanes of a pair are active together
        unsigned mask = __activemask();
#pragma unroll
        for (int r = 0; r < 3; r++)
#pragma unroll
            for (int c = 0; c < 3; c++)
                S[r][c] += __shfl_xor_sync(mask, S[r][c], 1);
        epart += __shfl_xor_sync(mask, epart, 1);

        // regularization term
        {
            float dx = ptx - p0x, dy = pty - p0y, dz = ptz - p0z;
            contrib = epart + LAMBDA_REG_LEN * (dx * dx + dy * dy + dz * dz);
        }

        float ssq = 0.0f;
#pragma unroll
        for (int r = 0; r < 3; r++)
#pragma unroll
            for (int c = 0; c < 3; c++)
                ssq += S[r][c] * S[r][c];

        float R[3][3] = {{1, 0, 0}, {0, 1, 0}, {0, 0, 1}};

        if (ssq > 1e-20f) {
            float A[3][3];
#pragma unroll
            for (int a = 0; a < 3; a++)
#pragma unroll
                for (int b = 0; b < 3; b++)
                    A[a][b] = S[0][a] * S[0][b] + S[1][a] * S[1][b] + S[2][a] * S[2][b];

            float V[3][3] = {{1, 0, 0}, {0, 1, 0}, {0, 0, 1}};
#pragma unroll
            for (int sweep = 0; sweep < 3; sweep++) {
                jrot<0, 1>(A, V);
                jrot<0, 2>(A, V);
                jrot<1, 2>(A, V);
            }

            float l0 = A[0][0], l1 = A[1][1], l2 = A[2][2];
            float tmp;
#define SWAPCOL(a, b)                                              \
    do {                                                           \
        tmp = V[0][a]; V[0][a] = V[0][b]; V[0][b] = tmp;           \
        tmp = V[1][a]; V[1][a] = V[1][b]; V[1][b] = tmp;           \
        tmp = V[2][a]; V[2][a] = V[2][b]; V[2][b] = tmp;           \
    } while (0)
            if (l0 < l1) { tmp = l0; l0 = l1; l1 = tmp; SWAPCOL(0, 1); }
            if (l0 < l2) { tmp = l0; l0 = l2; l2 = tmp; SWAPCOL(0, 2); }
            if (l1 < l2) { tmp = l1; l1 = l2; l2 = tmp; SWAPCOL(1, 2); }
#undef SWAPCOL

            float detV =
                V[0][0] * (V[1][1] * V[2][2] - V[1][2] * V[2][1]) -
                V[0][1] * (V[1][0] * V[2][2] - V[1][2] * V[2][0]) +
                V[0][2] * (V[1][0] * V[2][1] - V[1][1] * V[2][0]);
            if (detV < 0.0f) { V[0][2] = -V[0][2]; V[1][2] = -V[1][2]; V[2][2] = -V[2][2]; }

            float u1x = S[0][0] * V[0][0] + S[0][1] * V[1][0] + S[0][2] * V[2][0];
            float u1y = S[1][0] * V[0][0] + S[1][1] * V[1][0] + S[1][2] * V[2][0];
            float u1z = S[2][0] * V[0][0] + S[2][1] * V[1][0] + S[2][2] * V[2][0];
            float n1  = sqrtf(u1x * u1x + u1y * u1y + u1z * u1z);

            if (n1 > 1e-12f) {
                float inv1 = 1.0f / n1;
                u1x *= inv1; u1y *= inv1; u1z *= inv1;

                float wx = S[0][0] * V[0][1] + S[0][1] * V[1][1] + S[0][2] * V[2][1];
                float wy = S[1][0] * V[0][1] + S[1][1] * V[1][1] + S[1][2] * V[2][1];
                float wz = S[2][0] * V[0][1] + S[2][1] * V[1][1] + S[2][2] * V[2][1];
                float dotw = wx * u1x + wy * u1y + wz * u1z;
                wx -= dotw * u1x; wy -= dotw * u1y; wz -= dotw * u1z;
                float n2 = sqrtf(wx * wx + wy * wy + wz * wz);

                float u2x, u2y, u2z;
                if (n2 > 1e-6f * n1) {
                    float inv2 = 1.0f / n2;
                    u2x = wx * inv2; u2y = wy * inv2; u2z = wz * inv2;
                } else {
                    float ax = fabsf(u1x), ay = fabsf(u1y), az = fabsf(u1z);
                    float ex = 0, ey = 0, ez = 0;
                    if (ax <= ay && ax <= az) ex = 1.0f;
                    else if (ay <= az)        ey = 1.0f;
                    else                      ez = 1.0f;
                    float cx = u1y * ez - u1z * ey;
                    float cy = u1z * ex - u1x * ez;
                    float cz = u1x * ey - u1y * ex;
                    float nc = rsqrtf(cx * cx + cy * cy + cz * cz);
                    u2x = cx * nc; u2y = cy * nc; u2z = cz * nc;
                }

                float u3x = u1y * u2z - u1z * u2y;
                float u3y = u1z * u2x - u1x * u2z;
                float u3z = u1x * u2y - u1y * u2x;

                R[0][0] = u1x * V[0][0] + u2x * V[0][1] + u3x * V[0][2];
                R[0][1] = u1x * V[1][0] + u2x * V[1][1] + u3x * V[1][2];
                R[0][2] = u1x * V[2][0] + u2x * V[2][1] + u3x * V[2][2];
                R[1][0] = u1y * V[0][0] + u2y * V[0][1] + u3y * V[0][2];
                R[1][1] = u1y * V[1][0] + u2y * V[1][1] + u3y * V[1][2];
                R[1][2] = u1y * V[2][0] + u2y * V[2][1] + u3y * V[2][2];
                R[2][0] = u1z * V[0][0] + u2z * V[0][1] + u3z * V[0][2];
                R[2][1] = u1z * V[1][0] + u2z * V[1][1] + u3z * V[1][2];
                R[2][2] = u1z * V[2][0] + u2z * V[2][1] + u3z * V[2][2];
            }
        }

        // cross term: -<R, S>
        float cross = 0.0f;
#pragma unroll
        for (int r = 0; r < 3; r++)
#pragma unroll
            for (int c = 0; c < 3; c++)
                cross += R[r][c] * S[r][c];
        contrib -= cross;

        // rotation -> quaternion (w, x, y, z); sign irrelevant downstream
        float qw, qx, qy, qz;
        float tr = R[0][0] + R[1][1] + R[2][2];
        if (tr > 0.0f) {
            float s = sqrtf(tr + 1.0f) * 2.0f;
            qw = 0.25f * s;
            qx = (R[2][1] - R[1][2]) / s;
            qy = (R[0][2] - R[2][0]) / s;
            qz = (R[1][0] - R[0][1]) / s;
        } else if (R[0][0] > R[1][1] && R[0][0] > R[2][2]) {
            float s = sqrtf(1.0f + R[0][0] - R[1][1] - R[2][2]) * 2.0f;
            qw = (R[2][1] - R[1][2]) / s;
            qx = 0.25f * s;
            qy = (R[0][1] + R[1][0]) / s;
            qz = (R[0][2] + R[2][0]) / s;
        } else if (R[1][1] > R[2][2]) {
            float s = sqrtf(1.0f + R[1][1] - R[0][0] - R[2][2]) * 2.0f;
            qw = (R[0][2] - R[2][0]) / s;
            qx = (R[0][1] + R[1][0]) / s;
            qy = 0.25f * s;
            qz = (R[1][2] + R[2][1]) / s;
        } else {
            float s = sqrtf(1.0f + R[2][2] - R[0][0] - R[1][1]) * 2.0f;
            qw = (R[1][0] - R[0][1]) / s;
            qx = (R[0][2] + R[2][0]) / s;
            qy = (R[1][2] + R[2][1]) / s;
            qz = 0.25f * s;
        }

        if (par == 0) {
            float4 eq;
            eq.x = pack2(qw, qx);
            eq.y = pack2(qy, qz);
            eq.z = pack2(p0x, p0y);
            eq.w = pack2(p0z, 0.f);
            g_EQ[v] = eq;
        } else {
            contrib = 0.0f;   // counted once per vertex (even lane)
        }
    }

    block_reduce_to_acc(contrib);
}

// ---------------------------------------------------------------------------
// Kernel 4: per-edge rotation-coupling term 0.5 * (R_i d0) . (R_j d0).
// ---------------------------------------------------------------------------
__device__ __forceinline__ void quat_rot(float w, float ux, float uy, float uz,
                                         float vx, float vy, float vz,
                                         float& ox, float& oy, float& oz)
{
    float tx = 2.0f * (uy * vz - uz * vy);
    float ty = 2.0f * (uz * vx - ux * vz);
    float tz = 2.0f * (ux * vy - uy * vx);
    ox = vx + w * tx + (uy * tz - uz * ty);
    oy = vy + w * ty + (uz * tx - ux * tz);
    oz = vz + w * tz + (ux * ty - uy * tx);
}

__global__ void k_energy(const void* __restrict__ neigh, int n_edge)
{
    int e = blockIdx.x * blockDim.x + threadIdx.x;
    float loc = 0.0f;

    if (e < n_edge) {
        int idx64 = g_idx64;
        int i, j;
        load_edge(neigh, e, idx64, i, j);

        float4 ei = g_EQ[i];
        float4 ej = g_EQ[j];

        float2 qa = unpack2(ei.x), qb = unpack2(ei.y);
        float2 oa = unpack2(ei.z), ob = unpack2(ei.w);
        float2 ra = unpack2(ej.x), rb = unpack2(ej.y);
        float2 pa = unpack2(ej.z), pb = unpack2(ej.w);

        float d00 = oa.x - pa.x, d01 = oa.y - pa.y, d02 = ob.x - pb.x;

        float px, py, pz, rx, ry, rz;
        quat_rot(qa.x, qa.y, qb.x, qb.y, d00, d01, d02, px, py, pz);
        quat_rot(ra.x, ra.y, rb.x, rb.y, d00, d01, d02, rx, ry, rz);

        loc = 0.5f * (px * rx + py * ry + pz * rz);
    }

    block_reduce_to_acc(loc);
}

// ---------------------------------------------------------------------------
// Kernel 5: write scalar output
// ---------------------------------------------------------------------------
__global__ void k_write(float* out)
{
    out[0] = (float)g_acc;
}

// ---------------------------------------------------------------------------
extern "C" void kernel_launch(void* const* d_in, const int* in_sizes, int n_in,
                              void* d_out, int out_size)
{
    const float* vt    = (const float*)d_in[0];
    const float* v0    = (const float*)d_in[1];
    const void*  neigh = d_in[2];

    int n_vert = in_sizes[0] / 3;
    int n_edge = in_sizes[2] / 2;
    int half   = (n_edge + 1) / 2;

    const int B = 256;

    k_pack<<<(n_vert + B - 1) / B, B>>>(vt, v0, (const unsigned int*)neigh,
                                        in_sizes[2], n_vert);
    k_fill<<<(half + B - 1) / B, B>>>(neigh, n_edge, half);
    k_svd<<<(2 * n_vert + B - 1) / B, B>>>(n_vert);
    k_energy<<<(n_edge + B - 1) / B, B>>>(neigh, n_edge);
    k_write<<<1, 1>>>((float*)d_out);
}

// round 15
// speedup vs baseline: 1.1049x; 1.1049x over previous
#include <cuda_runtime.h>
#include <cuda_fp16.h>
#include <math.h>

#define MAX_VERT 500000
#define ELL_CAP 48
#define LAMBDA_REG_LEN 1e-6f

// scratch (no cudaMalloc allowed)
__device__ double g_acc;
__device__ int    g_idx64;                 // 1 if neigh is int64, 0 if int32
__device__ int    g_deg[MAX_VERT];
// slot-major ELL: g_ell[slot * MAX_VERT + v] -> coalesced reads in k_svd
__device__ __align__(16) int    g_ell[ELL_CAP * MAX_VERT];
// packed fp16 mesh: (vt.x,vt.y)(vt.z,v0.x)(v0.y,v0.z)(pad) per vertex, 16B
__device__ __align__(16) float4 g_PH[MAX_VERT];
// packed fp16 (quat w,x)(quat y,z)(v0.x,v0.y)(v0.z,pad) per vertex, 16B
__device__ __align__(16) float4 g_EQ[MAX_VERT];

// ---------------------------------------------------------------------------
// fp16 pack/unpack helpers
// ---------------------------------------------------------------------------
__device__ __forceinline__ float pack2(float a, float b)
{
    __half2 h = __floats2half2_rn(a, b);
    return __uint_as_float(*reinterpret_cast<unsigned*>(&h));
}
__device__ __forceinline__ float2 unpack2(float f)
{
    unsigned u = __float_as_uint(f);
    __half2 h = *reinterpret_cast<__half2*>(&u);
    return __half22float2(h);
}

__device__ __forceinline__ void load_edge(const void* __restrict__ neigh,
                                          int e, int idx64, int& i, int& j)
{
    if (idx64) {
        const longlong2* p = (const longlong2*)neigh;
        longlong2 v = p[e];
        i = (int)v.x;
        j = (int)v.y;
    } else {
        const int2* p = (const int2*)neigh;
        int2 v = p[e];
        i = v.x;
        j = v.y;
    }
}

__device__ __forceinline__ void block_reduce_to_acc(float val)
{
    __shared__ float sdata[256];
    int tid = threadIdx.x;
    sdata[tid] = val;
    __syncthreads();
    for (int s = 128; s > 0; s >>= 1) {
        if (tid < s) sdata[tid] += sdata[tid + s];
        __syncthreads();
    }
    if (tid == 0)
        atomicAdd(&g_acc, (double)sdata[0]);
}

// ---------------------------------------------------------------------------
// Kernel 1: pack vertex arrays into fp16 records; zero degrees.
// Block 0 additionally performs the index-dtype detection (int64 LE => all
// odd 32-bit words of neigh are zero) and resets the accumulator.
// ---------------------------------------------------------------------------
__global__ void k_pack(const float* __restrict__ vt,
                       const float* __restrict__ v0,
                       const unsigned int* __restrict__ neigh_raw,
                       int n_words,
                       int n_vert)
{
    if (blockIdx.x == 0) {
        __shared__ int any_nonzero;
        if (threadIdx.x == 0) any_nonzero = 0;
        __syncthreads();
        int limit = n_words < 2048 ? n_words : 2048;
        for (int w = threadIdx.x; w < limit; w += blockDim.x) {
            if ((w & 1) && neigh_raw[w] != 0u) atomicOr(&any_nonzero, 1);
        }
        __syncthreads();
        if (threadIdx.x == 0) {
            g_idx64 = any_nonzero ? 0 : 1;
            g_acc   = 0.0;
        }
    }

    int v = blockIdx.x * blockDim.x + threadIdx.x;
    if (v >= n_vert) return;
    float tx = vt[3 * v], ty = vt[3 * v + 1], tz = vt[3 * v + 2];
    float ox = v0[3 * v], oy = v0[3 * v + 1], oz = v0[3 * v + 2];
    float4 r;
    r.x = pack2(tx, ty);
    r.y = pack2(tz, ox);
    r.z = pack2(oy, oz);
    r.w = 0.f;
    g_PH[v]  = r;
    g_deg[v] = 0;
}

// ---------------------------------------------------------------------------
// Kernel 2: build ELL adjacency (slot-major), two edges per thread.
// ---------------------------------------------------------------------------
__global__ void k_fill(const void* __restrict__ neigh, int n_edge, int half)
{
    int e0 = blockIdx.x * blockDim.x + threadIdx.x;
    if (e0 >= half) return;
    int e1 = e0 + half;
    bool has1 = (e1 < n_edge);

    int idx64 = g_idx64;
    int i0, j0, i1 = 0, j1 = 0;
    load_edge(neigh, e0, idx64, i0, j0);
    if (has1) load_edge(neigh, e1, idx64, i1, j1);

    int p0 = atomicAdd(&g_deg[i0], 1);
    int q0 = atomicAdd(&g_deg[j0], 1);
    int p1 = 0, q1 = 0;
    if (has1) {
        p1 = atomicAdd(&g_deg[i1], 1);
        q1 = atomicAdd(&g_deg[j1], 1);
    }

    if (p0 < ELL_CAP) g_ell[p0 * MAX_VERT + i0] = j0;
    if (q0 < ELL_CAP) g_ell[q0 * MAX_VERT + j0] = i0;
    if (has1) {
        if (p1 < ELL_CAP) g_ell[p1 * MAX_VERT + i1] = j1;
        if (q1 < ELL_CAP) g_ell[q1 * MAX_VERT + j1] = i1;
    }
}

// ---------------------------------------------------------------------------
// Kernel 3: fused gather + SVD on the fp16-rounded mesh (one thread/vertex).
// ---------------------------------------------------------------------------
template <int p, int q>
__device__ __forceinline__ void jrot(float (&A)[3][3], float (&V)[3][3])
{
    float apq = A[p][q];
    if (fabsf(apq) < 1e-30f) return;
    float tau = (A[q][q] - A[p][p]) * 0.5f / apq;
    float t   = copysignf(1.0f, tau) / (fabsf(tau) + sqrtf(1.0f + tau * tau));
    float c   = rsqrtf(1.0f + t * t);
    float s   = t * c;

    constexpr int k = 3 - p - q;
    float akp = A[k][p], akq = A[k][q];
    float nkp = c * akp - s * akq;
    float nkq = s * akp + c * akq;
    A[k][p] = nkp; A[p][k] = nkp;
    A[k][q] = nkq; A[q][k] = nkq;
    A[p][p] = A[p][p] - t * apq;
    A[q][q] = A[q][q] + t * apq;
    A[p][q] = 0.0f; A[q][p] = 0.0f;

#pragma unroll
    for (int r = 0; r < 3; r++) {
        float vp = V[r][p], vq = V[r][q];
        V[r][p] = c * vp - s * vq;
        V[r][q] = s * vp + c * vq;
    }
}

__device__ __forceinline__ void decode_ph(float4 r,
                                          float& tx, float& ty, float& tz,
                                          float& ox, float& oy, float& oz)
{
    float2 a = unpack2(r.x);
    float2 b = unpack2(r.y);
    float2 c = unpack2(r.z);
    tx = a.x; ty = a.y; tz = b.x;
    ox = b.y; oy = c.x; oz = c.y;
}

__global__ void k_svd(int n_vert)
{
    int v = blockIdx.x * blockDim.x + threadIdx.x;
    float contrib = 0.0f;

    if (v < n_vert) {
        float ptx, pty, ptz, p0x, p0y, p0z;
        decode_ph(g_PH[v], ptx, pty, ptz, p0x, p0y, p0z);

        int deg = g_deg[v];
        if (deg > ELL_CAP) deg = ELL_CAP;
        int padded = (deg + 3) & ~3;

        float S[3][3] = {{0, 0, 0}, {0, 0, 0}, {0, 0, 0}};
        float epart = 0.0f;

        for (int base = 0; base < padded; base += 4) {
            int ids[4];
#pragma unroll
            for (int t = 0; t < 4; t++) {
                int slot = base + t;
                ids[t] = (slot < deg) ? g_ell[slot * MAX_VERT + v] : v;
            }
            float4 ph[4];
#pragma unroll
            for (int t = 0; t < 4; t++) ph[t] = g_PH[ids[t]];
#pragma unroll
            for (int t = 0; t < 4; t++) {
                float qtx, qty, qtz, q0x, q0y, q0z;
                decode_ph(ph[t], qtx, qty, qtz, q0x, q0y, q0z);
                float dt0 = ptx - qtx, dt1 = pty - qty, dt2 = ptz - qtz;
                float d00 = p0x - q0x, d01 = p0y - q0y, d02 = p0z - q0z;
                S[0][0] += dt0 * d00; S[0][1] += dt0 * d01; S[0][2] += dt0 * d02;
                S[1][0] += dt1 * d00; S[1][1] += dt1 * d01; S[1][2] += dt1 * d02;
                S[2][0] += dt2 * d00; S[2][1] += dt2 * d01; S[2][2] += dt2 * d02;
                epart += 0.5f  * (dt0 * dt0 + dt1 * dt1 + dt2 * dt2)
                       + 0.25f * (d00 * d00 + d01 * d01 + d02 * d02);
            }
        }

        // regularization term
        {
            float dx = ptx - p0x, dy = pty - p0y, dz = ptz - p0z;
            contrib = epart + LAMBDA_REG_LEN * (dx * dx + dy * dy + dz * dz);
        }

        float ssq = 0.0f;
#pragma unroll
        for (int r = 0; r < 3; r++)
#pragma unroll
            for (int c = 0; c < 3; c++)
                ssq += S[r][c] * S[r][c];

        float R[3][3] = {{1, 0, 0}, {0, 1, 0}, {0, 0, 1}};

        if (ssq > 1e-20f) {
            float A[3][3];
#pragma unroll
            for (int a = 0; a < 3; a++)
#pragma unroll
                for (int b = 0; b < 3; b++)
                    A[a][b] = S[0][a] * S[0][b] + S[1][a] * S[1][b] + S[2][a] * S[2][b];

            float V[3][3] = {{1, 0, 0}, {0, 1, 0}, {0, 0, 1}};
            // 3 cyclic sweeps: off-diag ~1e-10; energy error is 2nd order in
            // the rotation error (R is the minimizer), so this is safe.
#pragma unroll
            for (int sweep = 0; sweep < 3; sweep++) {
                jrot<0, 1>(A, V);
                jrot<0, 2>(A, V);
                jrot<1, 2>(A, V);
            }

            float l0 = A[0][0], l1 = A[1][1], l2 = A[2][2];
            float tmp;
#define SWAPCOL(a, b)                                              \
    do {                                                           \
        tmp = V[0][a]; V[0][a] = V[0][b]; V[0][b] = tmp;           \
        tmp = V[1][a]; V[1][a] = V[1][b]; V[1][b] = tmp;           \
        tmp = V[2][a]; V[2][a] = V[2][b]; V[2][b] = tmp;           \
    } while (0)
            if (l0 < l1) { tmp = l0; l0 = l1; l1 = tmp; SWAPCOL(0, 1); }
            if (l0 < l2) { tmp = l0; l0 = l2; l2 = tmp; SWAPCOL(0, 2); }
            if (l1 < l2) { tmp = l1; l1 = l2; l2 = tmp; SWAPCOL(1, 2); }
#undef SWAPCOL

            float detV =
                V[0][0] * (V[1][1] * V[2][2] - V[1][2] * V[2][1]) -
                V[0][1] * (V[1][0] * V[2][2] - V[1][2] * V[2][0]) +
                V[0][2] * (V[1][0] * V[2][1] - V[1][1] * V[2][0]);
            if (detV < 0.0f) { V[0][2] = -V[0][2]; V[1][2] = -V[1][2]; V[2][2] = -V[2][2]; }

            float u1x = S[0][0] * V[0][0] + S[0][1] * V[1][0] + S[0][2] * V[2][0];
            float u1y = S[1][0] * V[0][0] + S[1][1] * V[1][0] + S[1][2] * V[2][0];
            float u1z = S[2][0] * V[0][0] + S[2][1] * V[1][0] + S[2][2] * V[2][0];
            float n1  = sqrtf(u1x * u1x + u1y * u1y + u1z * u1z);

            if (n1 > 1e-12f) {
                float inv1 = 1.0f / n1;
                u1x *= inv1; u1y *= inv1; u1z *= inv1;

                float wx = S[0][0] * V[0][1] + S[0][1] * V[1][1] + S[0][2] * V[2][1];
                float wy = S[1][0] * V[0][1] + S[1][1] * V[1][1] + S[1][2] * V[2][1];
                float wz = S[2][0] * V[0][1] + S[2][1] * V[1][1] + S[2][2] * V[2][1];
                float dotw = wx * u1x + wy * u1y + wz * u1z;
                wx -= dotw * u1x; wy -= dotw * u1y; wz -= dotw * u1z;
                float n2 = sqrtf(wx * wx + wy * wy + wz * wz);

                float u2x, u2y, u2z;
                if (n2 > 1e-6f * n1) {
                    float inv2 = 1.0f / n2;
                    u2x = wx * inv2; u2y = wy * inv2; u2z = wz * inv2;
                } else {
                    float ax = fabsf(u1x), ay = fabsf(u1y), az = fabsf(u1z);
                    float ex = 0, ey = 0, ez = 0;
                    if (ax <= ay && ax <= az) ex = 1.0f;
                    else if (ay <= az)        ey = 1.0f;
                    else                      ez = 1.0f;
                    float cx = u1y * ez - u1z * ey;
                    float cy = u1z * ex - u1x * ez;
                    float cz = u1x * ey - u1y * ex;
                    float nc = rsqrtf(cx * cx + cy * cy + cz * cz);
                    u2x = cx * nc; u2y = cy * nc; u2z = cz * nc;
                }

                float u3x = u1y * u2z - u1z * u2y;
                float u3y = u1z * u2x - u1x * u2z;
                float u3z = u1x * u2y - u1y * u2x;

                R[0][0] = u1x * V[0][0] + u2x * V[0][1] + u3x * V[0][2];
                R[0][1] = u1x * V[1][0] + u2x * V[1][1] + u3x * V[1][2];
                R[0][2] = u1x * V[2][0] + u2x * V[2][1] + u3x * V[2][2];
                R[1][0] = u1y * V[0][0] + u2y * V[0][1] + u3y * V[0][2];
                R[1][1] = u1y * V[1][0] + u2y * V[1][1] + u3y * V[1][2];
                R[1][2] = u1y * V[2][0] + u2y * V[2][1] + u3y * V[2][2];
                R[2][0] = u1z * V[0][0] + u2z * V[0][1] + u3z * V[0][2];
                R[2][1] = u1z * V[1][0] + u2z * V[1][1] + u3z * V[1][2];
                R[2][2] = u1z * V[2][0] + u2z * V[2][1] + u3z * V[2][2];
            }
        }

        // cross term: -<R, S>
        float cross = 0.0f;
#pragma unroll
        for (int r = 0; r < 3; r++)
#pragma unroll
            for (int c = 0; c < 3; c++)
                cross += R[r][c] * S[r][c];
        contrib -= cross;

        // rotation -> quaternion (w, x, y, z); sign irrelevant downstream
        float qw, qx, qy, qz;
        float tr = R[0][0] + R[1][1] + R[2][2];
        if (tr > 0.0f) {
            float s = sqrtf(tr + 1.0f) * 2.0f;
            qw = 0.25f * s;
            qx = (R[2][1] - R[1][2]) / s;
            qy = (R[0][2] - R[2][0]) / s;
            qz = (R[1][0] - R[0][1]) / s;
        } else if (R[0][0] > R[1][1] && R[0][0] > R[2][2]) {
            float s = sqrtf(1.0f + R[0][0] - R[1][1] - R[2][2]) * 2.0f;
            qw = (R[2][1] - R[1][2]) / s;
            qx = 0.25f * s;
            qy = (R[0][1] + R[1][0]) / s;
            qz = (R[0][2] + R[2][0]) / s;
        } else if (R[1][1] > R[2][2]) {
            float s = sqrtf(1.0f + R[1][1] - R[0][0] - R[2][2]) * 2.0f;
            qw = (R[0][2] - R[2][0]) / s;
            qx = (R[0][1] + R[1][0]) / s;
            qy = 0.25f * s;
            qz = (R[1][2] + R[2][1]) / s;
        } else {
            float s = sqrtf(1.0f + R[2][2] - R[0][0] - R[1][1]) * 2.0f;
            qw = (R[1][0] - R[0][1]) / s;
            qx = (R[0][2] + R[2][0]) / s;
            qy = (R[1][2] + R[2][1]) / s;
            qz = 0.25f * s;
        }

        // pack (quat fp16, v0 fp16) for the energy pass
        float4 eq;
        eq.x = pack2(qw, qx);
        eq.y = pack2(qy, qz);
        eq.z = pack2(p0x, p0y);
        eq.w = pack2(p0z, 0.f);
        g_EQ[v] = eq;
    }

    block_reduce_to_acc(contrib);
}

// ---------------------------------------------------------------------------
// Kernel 4: per-edge rotation-coupling term 0.5 * (R_i d0) . (R_j d0).
// Two edges per thread: 4 independent divergent loads in flight before any
// consumption -> hides L2 round-trip in the issue-slack (issue was 34%).
// ---------------------------------------------------------------------------
__device__ __forceinline__ void quat_rot(float w, float ux, float uy, float uz,
                                         float vx, float vy, float vz,
                                         float& ox, float& oy, float& oz)
{
    float tx = 2.0f * (uy * vz - uz * vy);
    float ty = 2.0f * (uz * vx - ux * vz);
    float tz = 2.0f * (ux * vy - uy * vx);
    ox = vx + w * tx + (uy * tz - uz * ty);
    oy = vy + w * ty + (uz * tx - ux * tz);
    oz = vz + w * tz + (ux * ty - uy * tx);
}

__device__ __forceinline__ float edge_term(float4 ei, float4 ej)
{
    float2 qa = unpack2(ei.x), qb = unpack2(ei.y);
    float2 oa = unpack2(ei.z), ob = unpack2(ei.w);
    float2 ra = unpack2(ej.x), rb = unpack2(ej.y);
    float2 pa = unpack2(ej.z), pb = unpack2(ej.w);

    float d00 = oa.x - pa.x, d01 = oa.y - pa.y, d02 = ob.x - pb.x;

    float px, py, pz, rx, ry, rz;
    quat_rot(qa.x, qa.y, qb.x, qb.y, d00, d01, d02, px, py, pz);
    quat_rot(ra.x, ra.y, rb.x, rb.y, d00, d01, d02, rx, ry, rz);

    return 0.5f * (px * rx + py * ry + pz * rz);
}

__global__ void k_energy(const void* __restrict__ neigh, int n_edge, int half)
{
    int e0 = blockIdx.x * blockDim.x + threadIdx.x;
    float loc = 0.0f;

    if (e0 < half) {
        int idx64 = g_idx64;
        int e1 = e0 + half;
        bool has1 = (e1 < n_edge);

        int i0, j0, i1 = 0, j1 = 0;
        load_edge(neigh, e0, idx64, i0, j0);
        if (has1) load_edge(neigh, e1, idx64, i1, j1);

        // batch all divergent loads before consuming
        float4 a0 = g_EQ[i0];
        float4 b0 = g_EQ[j0];
        float4 a1, b1;
        if (has1) { a1 = g_EQ[i1]; b1 = g_EQ[j1]; }

        loc = edge_term(a0, b0);
        if (has1) loc += edge_term(a1, b1);
    }

    block_reduce_to_acc(loc);
}

// ---------------------------------------------------------------------------
// Kernel 5: write scalar output
// ---------------------------------------------------------------------------
__global__ void k_write(float* out)
{
    out[0] = (float)g_acc;
}

// ---------------------------------------------------------------------------
extern "C" void kernel_launch(void* const* d_in, const int* in_sizes, int n_in,
                              void* d_out, int out_size)
{
    const float* vt    = (const float*)d_in[0];
    const float* v0    = (const float*)d_in[1];
    const void*  neigh = d_in[2];

    int n_vert = in_sizes[0] / 3;
    int n_edge = in_sizes[2] / 2;
    int half   = (n_edge + 1) / 2;

    const int B = 256;

    k_pack<<<(n_vert + B - 1) / B, B>>>(vt, v0, (const unsigned int*)neigh,
                                        in_sizes[2], n_vert);
    k_fill<<<(half + B - 1) / B, B>>>(neigh, n_edge, half);
    k_svd<<<(n_vert + B - 1) / B, B>>>(n_vert);
    k_energy<<<(half + B - 1) / B, B>>>(neigh, n_edge, half);
    k_write<<<1, 1>>>((float*)d_out);
}

// round 16
// speedup vs baseline: 1.1165x; 1.0105x over previous
#include <cuda_runtime.h>
#include <cuda_fp16.h>
#include <math.h>

#define MAX_VERT 500000
#define ELL_CAP 48
#define LAMBDA_REG_LEN 1e-6f

// scratch (no cudaMalloc allowed)
__device__ double g_acc;
__device__ int    g_idx64;                 // 1 if neigh is int64, 0 if int32
__device__ int    g_deg[MAX_VERT];
// slot-major ELL: g_ell[slot * MAX_VERT + v] -> coalesced reads in k_svd
__device__ __align__(16) int    g_ell[ELL_CAP * MAX_VERT];
// packed fp16 mesh: (vt.x,vt.y)(vt.z,v0.x)(v0.y,v0.z)(pad) per vertex, 16B
__device__ __align__(16) float4 g_PH[MAX_VERT];
// packed fp16 (quat w,x)(quat y,z)(v0.x,v0.y)(v0.z,pad) per vertex, 16B
__device__ __align__(16) float4 g_EQ[MAX_VERT];

// ---------------------------------------------------------------------------
// fp16 pack/unpack helpers
// ---------------------------------------------------------------------------
__device__ __forceinline__ float pack2(float a, float b)
{
    __half2 h = __floats2half2_rn(a, b);
    return __uint_as_float(*reinterpret_cast<unsigned*>(&h));
}
__device__ __forceinline__ float2 unpack2(float f)
{
    unsigned u = __float_as_uint(f);
    __half2 h = *reinterpret_cast<__half2*>(&u);
    return __half22float2(h);
}

__device__ __forceinline__ void load_edge(const void* __restrict__ neigh,
                                          int e, int idx64, int& i, int& j)
{
    if (idx64) {
        const longlong2* p = (const longlong2*)neigh;
        longlong2 v = p[e];
        i = (int)v.x;
        j = (int)v.y;
    } else {
        const int2* p = (const int2*)neigh;
        int2 v = p[e];
        i = v.x;
        j = v.y;
    }
}

__device__ __forceinline__ void block_reduce_to_acc(float val)
{
    __shared__ float sdata[256];
    int tid = threadIdx.x;
    sdata[tid] = val;
    __syncthreads();
    for (int s = 128; s > 0; s >>= 1) {
        if (tid < s) sdata[tid] += sdata[tid + s];
        __syncthreads();
    }
    if (tid == 0)
        atomicAdd(&g_acc, (double)sdata[0]);
}

// ---------------------------------------------------------------------------
// Kernel 1: pack vertex arrays into fp16 records; zero degrees.
// Block 0 additionally performs the index-dtype detection (int64 LE => all
// odd 32-bit words of neigh are zero) and resets the accumulator.
// ---------------------------------------------------------------------------
__global__ void k_pack(const float* __restrict__ vt,
                       const float* __restrict__ v0,
                       const unsigned int* __restrict__ neigh_raw,
                       int n_words,
                       int n_vert)
{
    if (blockIdx.x == 0) {
        __shared__ int any_nonzero;
        if (threadIdx.x == 0) any_nonzero = 0;
        __syncthreads();
        int limit = n_words < 2048 ? n_words : 2048;
        for (int w = threadIdx.x; w < limit; w += blockDim.x) {
            if ((w & 1) && neigh_raw[w] != 0u) atomicOr(&any_nonzero, 1);
        }
        __syncthreads();
        if (threadIdx.x == 0) {
            g_idx64 = any_nonzero ? 0 : 1;
            g_acc   = 0.0;
        }
    }

    int v = blockIdx.x * blockDim.x + threadIdx.x;
    if (v >= n_vert) return;
    float tx = vt[3 * v], ty = vt[3 * v + 1], tz = vt[3 * v + 2];
    float ox = v0[3 * v], oy = v0[3 * v + 1], oz = v0[3 * v + 2];
    float4 r;
    r.x = pack2(tx, ty);
    r.y = pack2(tz, ox);
    r.z = pack2(oy, oz);
    r.w = 0.f;
    g_PH[v]  = r;
    g_deg[v] = 0;
}

// ---------------------------------------------------------------------------
// Kernel 2: build ELL adjacency (slot-major), two edges per thread.
// ---------------------------------------------------------------------------
__global__ void k_fill(const void* __restrict__ neigh, int n_edge, int half)
{
    int e0 = blockIdx.x * blockDim.x + threadIdx.x;
    if (e0 >= half) return;
    int e1 = e0 + half;
    bool has1 = (e1 < n_edge);

    int idx64 = g_idx64;
    int i0, j0, i1 = 0, j1 = 0;
    load_edge(neigh, e0, idx64, i0, j0);
    if (has1) load_edge(neigh, e1, idx64, i1, j1);

    int p0 = atomicAdd(&g_deg[i0], 1);
    int q0 = atomicAdd(&g_deg[j0], 1);
    int p1 = 0, q1 = 0;
    if (has1) {
        p1 = atomicAdd(&g_deg[i1], 1);
        q1 = atomicAdd(&g_deg[j1], 1);
    }

    if (p0 < ELL_CAP) g_ell[p0 * MAX_VERT + i0] = j0;
    if (q0 < ELL_CAP) g_ell[q0 * MAX_VERT + j0] = i0;
    if (has1) {
        if (p1 < ELL_CAP) g_ell[p1 * MAX_VERT + i1] = j1;
        if (q1 < ELL_CAP) g_ell[q1 * MAX_VERT + j1] = i1;
    }
}

// ---------------------------------------------------------------------------
// Kernel 3: fused gather + SVD on the fp16-rounded mesh (one thread/vertex).
// 8-slot gather batches: 8 independent divergent PH loads in flight.
// ---------------------------------------------------------------------------
template <int p, int q>
__device__ __forceinline__ void jrot(float (&A)[3][3], float (&V)[3][3])
{
    float apq = A[p][q];
    if (fabsf(apq) < 1e-30f) return;
    float tau = (A[q][q] - A[p][p]) * 0.5f / apq;
    float t   = copysignf(1.0f, tau) / (fabsf(tau) + sqrtf(1.0f + tau * tau));
    float c   = rsqrtf(1.0f + t * t);
    float s   = t * c;

    constexpr int k = 3 - p - q;
    float akp = A[k][p], akq = A[k][q];
    float nkp = c * akp - s * akq;
    float nkq = s * akp + c * akq;
    A[k][p] = nkp; A[p][k] = nkp;
    A[k][q] = nkq; A[q][k] = nkq;
    A[p][p] = A[p][p] - t * apq;
    A[q][q] = A[q][q] + t * apq;
    A[p][q] = 0.0f; A[q][p] = 0.0f;

#pragma unroll
    for (int r = 0; r < 3; r++) {
        float vp = V[r][p], vq = V[r][q];
        V[r][p] = c * vp - s * vq;
        V[r][q] = s * vp + c * vq;
    }
}

__device__ __forceinline__ void decode_ph(float4 r,
                                          float& tx, float& ty, float& tz,
                                          float& ox, float& oy, float& oz)
{
    float2 a = unpack2(r.x);
    float2 b = unpack2(r.y);
    float2 c = unpack2(r.z);
    tx = a.x; ty = a.y; tz = b.x;
    ox = b.y; oy = c.x; oz = c.y;
}

__global__ void k_svd(int n_vert)
{
    int v = blockIdx.x * blockDim.x + threadIdx.x;
    float contrib = 0.0f;

    if (v < n_vert) {
        float ptx, pty, ptz, p0x, p0y, p0z;
        decode_ph(g_PH[v], ptx, pty, ptz, p0x, p0y, p0z);

        int deg = g_deg[v];
        if (deg > ELL_CAP) deg = ELL_CAP;
        int padded = (deg + 7) & ~7;

        float S[3][3] = {{0, 0, 0}, {0, 0, 0}, {0, 0, 0}};
        float epart = 0.0f;

        for (int base = 0; base < padded; base += 8) {
            int ids[8];
#pragma unroll
            for (int t = 0; t < 8; t++) {
                int slot = base + t;
                ids[t] = (slot < deg) ? g_ell[slot * MAX_VERT + v] : v;
            }
            float4 ph[8];
#pragma unroll
            for (int t = 0; t < 8; t++) ph[t] = g_PH[ids[t]];
#pragma unroll
            for (int t = 0; t < 8; t++) {
                float qtx, qty, qtz, q0x, q0y, q0z;
                decode_ph(ph[t], qtx, qty, qtz, q0x, q0y, q0z);
                float dt0 = ptx - qtx, dt1 = pty - qty, dt2 = ptz - qtz;
                float d00 = p0x - q0x, d01 = p0y - q0y, d02 = p0z - q0z;
                S[0][0] += dt0 * d00; S[0][1] += dt0 * d01; S[0][2] += dt0 * d02;
                S[1][0] += dt1 * d00; S[1][1] += dt1 * d01; S[1][2] += dt1 * d02;
                S[2][0] += dt2 * d00; S[2][1] += dt2 * d01; S[2][2] += dt2 * d02;
                epart += 0.5f  * (dt0 * dt0 + dt1 * dt1 + dt2 * dt2)
                       + 0.25f * (d00 * d00 + d01 * d01 + d02 * d02);
            }
        }

        // regularization term
        {
            float dx = ptx - p0x, dy = pty - p0y, dz = ptz - p0z;
            contrib = epart + LAMBDA_REG_LEN * (dx * dx + dy * dy + dz * dz);
        }

        float ssq = 0.0f;
#pragma unroll
        for (int r = 0; r < 3; r++)
#pragma unroll
            for (int c = 0; c < 3; c++)
                ssq += S[r][c] * S[r][c];

        float R[3][3] = {{1, 0, 0}, {0, 1, 0}, {0, 0, 1}};

        if (ssq > 1e-20f) {
            float A[3][3];
#pragma unroll
            for (int a = 0; a < 3; a++)
#pragma unroll
                for (int b = 0; b < 3; b++)
                    A[a][b] = S[0][a] * S[0][b] + S[1][a] * S[1][b] + S[2][a] * S[2][b];

            float V[3][3] = {{1, 0, 0}, {0, 1, 0}, {0, 0, 1}};
#pragma unroll
            for (int sweep = 0; sweep < 3; sweep++) {
                jrot<0, 1>(A, V);
                jrot<0, 2>(A, V);
                jrot<1, 2>(A, V);
            }

            float l0 = A[0][0], l1 = A[1][1], l2 = A[2][2];
            float tmp;
#define SWAPCOL(a, b)                                              \
    do {                                                           \
        tmp = V[0][a]; V[0][a] = V[0][b]; V[0][b] = tmp;           \
        tmp = V[1][a]; V[1][a] = V[1][b]; V[1][b] = tmp;           \
        tmp = V[2][a]; V[2][a] = V[2][b]; V[2][b] = tmp;           \
    } while (0)
            if (l0 < l1) { tmp = l0; l0 = l1; l1 = tmp; SWAPCOL(0, 1); }
            if (l0 < l2) { tmp = l0; l0 = l2; l2 = tmp; SWAPCOL(0, 2); }
            if (l1 < l2) { tmp = l1; l1 = l2; l2 = tmp; SWAPCOL(1, 2); }
#undef SWAPCOL

            float detV =
                V[0][0] * (V[1][1] * V[2][2] - V[1][2] * V[2][1]) -
                V[0][1] * (V[1][0] * V[2][2] - V[1][2] * V[2][0]) +
                V[0][2] * (V[1][0] * V[2][1] - V[1][1] * V[2][0]);
            if (detV < 0.0f) { V[0][2] = -V[0][2]; V[1][2] = -V[1][2]; V[2][2] = -V[2][2]; }

            float u1x = S[0][0] * V[0][0] + S[0][1] * V[1][0] + S[0][2] * V[2][0];
            float u1y = S[1][0] * V[0][0] + S[1][1] * V[1][0] + S[1][2] * V[2][0];
            float u1z = S[2][0] * V[0][0] + S[2][1] * V[1][0] + S[2][2] * V[2][0];
            float n1  = sqrtf(u1x * u1x + u1y * u1y + u1z * u1z);

            if (n1 > 1e-12f) {
                float inv1 = 1.0f / n1;
                u1x *= inv1; u1y *= inv1; u1z *= inv1;

                float wx = S[0][0] * V[0][1] + S[0][1] * V[1][1] + S[0][2] * V[2][1];
                float wy = S[1][0] * V[0][1] + S[1][1] * V[1][1] + S[1][2] * V[2][1];
                float wz = S[2][0] * V[0][1] + S[2][1] * V[1][1] + S[2][2] * V[2][1];
                float dotw = wx * u1x + wy * u1y + wz * u1z;
                wx -= dotw * u1x; wy -= dotw * u1y; wz -= dotw * u1z;
                float n2 = sqrtf(wx * wx + wy * wy + wz * wz);

                float u2x, u2y, u2z;
                if (n2 > 1e-6f * n1) {
                    float inv2 = 1.0f / n2;
                    u2x = wx * inv2; u2y = wy * inv2; u2z = wz * inv2;
                } else {
                    float ax = fabsf(u1x), ay = fabsf(u1y), az = fabsf(u1z);
                    float ex = 0, ey = 0, ez = 0;
                    if (ax <= ay && ax <= az) ex = 1.0f;
                    else if (ay <= az)        ey = 1.0f;
                    else                      ez = 1.0f;
                    float cx = u1y * ez - u1z * ey;
                    float cy = u1z * ex - u1x * ez;
                    float cz = u1x * ey - u1y * ex;
                    float nc = rsqrtf(cx * cx + cy * cy + cz * cz);
                    u2x = cx * nc; u2y = cy * nc; u2z = cz * nc;
                }

                float u3x = u1y * u2z - u1z * u2y;
                float u3y = u1z * u2x - u1x * u2z;
                float u3z = u1x * u2y - u1y * u2x;

                R[0][0] = u1x * V[0][0] + u2x * V[0][1] + u3x * V[0][2];
                R[0][1] = u1x * V[1][0] + u2x * V[1][1] + u3x * V[1][2];
                R[0][2] = u1x * V[2][0] + u2x * V[2][1] + u3x * V[2][2];
                R[1][0] = u1y * V[0][0] + u2y * V[0][1] + u3y * V[0][2];
                R[1][1] = u1y * V[1][0] + u2y * V[1][1] + u3y * V[1][2];
                R[1][2] = u1y * V[2][0] + u2y * V[2][1] + u3y * V[2][2];
                R[2][0] = u1z * V[0][0] + u2z * V[0][1] + u3z * V[0][2];
                R[2][1] = u1z * V[1][0] + u2z * V[1][1] + u3z * V[1][2];
                R[2][2] = u1z * V[2][0] + u2z * V[2][1] + u3z * V[2][2];
            }
        }

        // cross term: -<R, S>
        float cross = 0.0f;
#pragma unroll
        for (int r = 0; r < 3; r++)
#pragma unroll
            for (int c = 0; c < 3; c++)
                cross += R[r][c] * S[r][c];
        contrib -= cross;

        // rotation -> quaternion (w, x, y, z); sign irrelevant downstream
        float qw, qx, qy, qz;
        float tr = R[0][0] + R[1][1] + R[2][2];
        if (tr > 0.0f) {
            float s = sqrtf(tr + 1.0f) * 2.0f;
            qw = 0.25f * s;
            qx = (R[2][1] - R[1][2]) / s;
            qy = (R[0][2] - R[2][0]) / s;
            qz = (R[1][0] - R[0][1]) / s;
        } else if (R[0][0] > R[1][1] && R[0][0] > R[2][2]) {
            float s = sqrtf(1.0f + R[0][0] - R[1][1] - R[2][2]) * 2.0f;
            qw = (R[2][1] - R[1][2]) / s;
            qx = 0.25f * s;
            qy = (R[0][1] + R[1][0]) / s;
            qz = (R[0][2] + R[2][0]) / s;
        } else if (R[1][1] > R[2][2]) {
            float s = sqrtf(1.0f + R[1][1] - R[0][0] - R[2][2]) * 2.0f;
            qw = (R[0][2] - R[2][0]) / s;
            qx = (R[0][1] + R[1][0]) / s;
            qy = 0.25f * s;
            qz = (R[1][2] + R[2][1]) / s;
        } else {
            float s = sqrtf(1.0f + R[2][2] - R[0][0] - R[1][1]) * 2.0f;
            qw = (R[1][0] - R[0][1]) / s;
            qx = (R[0][2] + R[2][0]) / s;
            qy = (R[1][2] + R[2][1]) / s;
            qz = 0.25f * s;
        }

        // pack (quat fp16, v0 fp16) for the energy pass
        float4 eq;
        eq.x = pack2(qw, qx);
        eq.y = pack2(qy, qz);
        eq.z = pack2(p0x, p0y);
        eq.w = pack2(p0z, 0.f);
        g_EQ[v] = eq;
    }

    block_reduce_to_acc(contrib);
}

// ---------------------------------------------------------------------------
// Kernel 4: per-edge rotation-coupling term 0.5 * (R_i d0) . (R_j d0).
// Four edges per thread: 8 independent divergent loads in flight.
// ---------------------------------------------------------------------------
__device__ __forceinline__ void quat_rot(float w, float ux, float uy, float uz,
                                         float vx, float vy, float vz,
                                         float& ox, float& oy, float& oz)
{
    float tx = 2.0f * (uy * vz - uz * vy);
    float ty = 2.0f * (uz * vx - ux * vz);
    float tz = 2.0f * (ux * vy - uy * vx);
    ox = vx + w * tx + (uy * tz - uz * ty);
    oy = vy + w * ty + (uz * tx - ux * tz);
    oz = vz + w * tz + (ux * ty - uy * tx);
}

__device__ __forceinline__ float edge_term(float4 ei, float4 ej)
{
    float2 qa = unpack2(ei.x), qb = unpack2(ei.y);
    float2 oa = unpack2(ei.z), ob = unpack2(ei.w);
    float2 ra = unpack2(ej.x), rb = unpack2(ej.y);
    float2 pa = unpack2(ej.z), pb = unpack2(ej.w);

    float d00 = oa.x - pa.x, d01 = oa.y - pa.y, d02 = ob.x - pb.x;

    float px, py, pz, rx, ry, rz;
    quat_rot(qa.x, qa.y, qb.x, qb.y, d00, d01, d02, px, py, pz);
    quat_rot(ra.x, ra.y, rb.x, rb.y, d00, d01, d02, rx, ry, rz);

    return 0.5f * (px * rx + py * ry + pz * rz);
}

__global__ void k_energy(const void* __restrict__ neigh, int n_edge, int quarter)
{
    int e0 = blockIdx.x * blockDim.x + threadIdx.x;
    float loc = 0.0f;

    if (e0 < quarter) {
        int idx64 = g_idx64;

        int ii[4], jj[4];
        bool has[4];
#pragma unroll
        for (int k = 0; k < 4; k++) {
            int e = e0 + k * quarter;
            has[k] = (e < n_edge);
            ii[k] = 0; jj[k] = 0;
            if (has[k]) load_edge(neigh, e, idx64, ii[k], jj[k]);
        }

        // batch all divergent loads before consuming (inactive slots load
        // a valid address; the result is discarded)
        float4 a[4], b[4];
#pragma unroll
        for (int k = 0; k < 4; k++) {
            a[k] = g_EQ[ii[k]];
            b[k] = g_EQ[jj[k]];
        }

#pragma unroll
        for (int k = 0; k < 4; k++)
            if (has[k]) loc += edge_term(a[k], b[k]);
    }

    block_reduce_to_acc(loc);
}

// ---------------------------------------------------------------------------
// Kernel 5: write scalar output
// ---------------------------------------------------------------------------
__global__ void k_write(float* out)
{
    out[0] = (float)g_acc;
}

// ---------------------------------------------------------------------------
extern "C" void kernel_launch(void* const* d_in, const int* in_sizes, int n_in,
                              void* d_out, int out_size)
{
    const float* vt    = (const float*)d_in[0];
    const float* v0    = (const float*)d_in[1];
    const void*  neigh = d_in[2];

    int n_vert  = in_sizes[0] / 3;
    int n_edge  = in_sizes[2] / 2;
    int half    = (n_edge + 1) / 2;
    int quarter = (n_edge + 3) / 4;

    const int B = 256;

    k_pack<<<(n_vert + B - 1) / B, B>>>(vt, v0, (const unsigned int*)neigh,
                                        in_sizes[2], n_vert);
    k_fill<<<(half + B - 1) / B, B>>>(neigh, n_edge, half);
    k_svd<<<(n_vert + B - 1) / B, B>>>(n_vert);
    k_energy<<<(quarter + B - 1) / B, B>>>(neigh, n_edge, quarter);
    k_write<<<1, 1>>>((float*)d_out);
}